// round 2
// baseline (speedup 1.0000x reference)
#include <cuda_runtime.h>

#define B_ 8
#define N_ 2048
#define D_ 128
#define KC 16

// Scratch (static __device__ arrays — no runtime allocation)
__device__ float g_S[B_ * N_ * D_];      // un-normalized sum_neighbors, 32 MB
__device__ int   g_deg[B_ * N_];         // nnz per cost row
__device__ float g_Wt[2 * D_ * D_];      // W transposed: Wt[f][d] = W[d][f]

typedef unsigned long long ull;

__device__ __forceinline__ ull pack2(float lo, float hi) {
    ull r; asm("mov.b64 %0, {%1,%2};" : "=l"(r) : "f"(lo), "f"(hi)); return r;
}
__device__ __forceinline__ void fma2(ull &d, ull a, ull b) {
    asm("fma.rn.f32x2 %0, %1, %2, %3;" : "=l"(d) : "l"(a), "l"(b), "l"(d));
}
__device__ __forceinline__ float2 unpack2(ull v) {
    float2 r; asm("mov.b64 {%0,%1}, %2;" : "=f"(r.x), "=f"(r.y) : "l"(v)); return r;
}

// ---------------------------------------------------------------------------
// prep: zero degree counters, transpose W into Wt[f][d]
// ---------------------------------------------------------------------------
__global__ void prep_kernel(const float* __restrict__ W) {
    int i = blockIdx.x * 256 + threadIdx.x;     // 128 blocks * 256 = 32768
    if (i < B_ * N_) g_deg[i] = 0;
    if (i < 2 * D_ * D_) {
        int f = i >> 7, d = i & 127;
        g_Wt[i] = W[d * 2 * D_ + f];
    }
}

// ---------------------------------------------------------------------------
// gemm1: S[b,j,d] = sum_i cost[b,i,j] * emb[b,i,d]; fused degree count.
// Block = 128 j x 128 d, 256 threads, 8x8 microtile, f32x2 accumulators.
// ---------------------------------------------------------------------------
__global__ __launch_bounds__(256, 2) void gemm1_kernel(
    const float* __restrict__ cost, const float* __restrict__ emb)
{
    __shared__ float As[KC][128];   // cost[i_tile][j_tile]
    __shared__ float Bs[KC][128];   // emb[i_tile][d]

    const int b = blockIdx.y;
    const int j0 = blockIdx.x * 128;
    const float* cB = cost + (size_t)b * N_ * N_;
    const float* eB = emb + (size_t)b * N_ * D_;

    const int t = threadIdx.x, lane = t & 31, w = t >> 5;  // 8 warps
    const int tx = t & 15, ty = t >> 4;

    ull acc[8][4];
    #pragma unroll
    for (int j = 0; j < 8; j++)
        #pragma unroll
        for (int p = 0; p < 4; p++) acc[j][p] = pack2(0.f, 0.f);

    for (int k0 = 0; k0 < N_; k0 += KC) {
        // warp w loads tile rows w and w+8 (each row = 128 contiguous floats)
        float4 a0 = *(const float4*)(cB + (size_t)(k0 + w) * N_ + j0 + lane * 4);
        float4 a1 = *(const float4*)(cB + (size_t)(k0 + w + 8) * N_ + j0 + lane * 4);
        float4 b0 = *(const float4*)(eB + (size_t)(k0 + w) * D_ + lane * 4);
        float4 b1 = *(const float4*)(eB + (size_t)(k0 + w + 8) * D_ + lane * 4);

        // fused degree: count nonzeros in this 128-wide slice of rows i
        int c0 = (a0.x != 0.f) + (a0.y != 0.f) + (a0.z != 0.f) + (a0.w != 0.f);
        int c1 = (a1.x != 0.f) + (a1.y != 0.f) + (a1.z != 0.f) + (a1.w != 0.f);
        c0 = __reduce_add_sync(0xffffffffu, c0);
        c1 = __reduce_add_sync(0xffffffffu, c1);
        if (lane == 0)      atomicAdd(&g_deg[b * N_ + k0 + w], c0);
        else if (lane == 1) atomicAdd(&g_deg[b * N_ + k0 + w + 8], c1);

        __syncthreads();
        *(float4*)&As[w][lane * 4] = a0;
        *(float4*)&As[w + 8][lane * 4] = a1;
        *(float4*)&Bs[w][lane * 4] = b0;
        *(float4*)&Bs[w + 8][lane * 4] = b1;
        __syncthreads();

        #pragma unroll
        for (int kk = 0; kk < KC; kk++) {
            float4 av0 = *(const float4*)&As[kk][ty * 4];
            float4 av1 = *(const float4*)&As[kk][64 + ty * 4];
            float4 bv0 = *(const float4*)&Bs[kk][tx * 4];
            float4 bv1 = *(const float4*)&Bs[kk][64 + tx * 4];
            ull bp[4] = { pack2(bv0.x, bv0.y), pack2(bv0.z, bv0.w),
                          pack2(bv1.x, bv1.y), pack2(bv1.z, bv1.w) };
            float aj[8] = { av0.x, av0.y, av0.z, av0.w,
                            av1.x, av1.y, av1.z, av1.w };
            #pragma unroll
            for (int j = 0; j < 8; j++) {
                ull ad = pack2(aj[j], aj[j]);
                #pragma unroll
                for (int p = 0; p < 4; p++) fma2(acc[j][p], ad, bp[p]);
            }
        }
    }

    // store S (un-normalized)
    #pragma unroll
    for (int j = 0; j < 8; j++) {
        int jj = (j < 4) ? (ty * 4 + j) : (64 + ty * 4 + (j - 4));
        float* Sr = g_S + ((size_t)(b * N_ + j0 + jj)) * D_;
        float2 p0 = unpack2(acc[j][0]), p1 = unpack2(acc[j][1]);
        float2 p2 = unpack2(acc[j][2]), p3 = unpack2(acc[j][3]);
        *(float4*)(Sr + tx * 4)      = make_float4(p0.x, p0.y, p1.x, p1.y);
        *(float4*)(Sr + 64 + tx * 4) = make_float4(p2.x, p2.y, p3.x, p3.y);
    }
}

// ---------------------------------------------------------------------------
// gemm2: out[n,d] = relu( sum_f X[n,f] * Wt[f,d] + bias[d] )
//   X[n,f] = (f < 128) ? emb[n,f] : S[n,f-128] / degree[n]
// Block = 128 n x 128 d, K=256; X tile transposed into smem on load.
// ---------------------------------------------------------------------------
__global__ __launch_bounds__(256, 2) void gemm2_kernel(
    const float* __restrict__ emb, const float* __restrict__ bias,
    float* __restrict__ out)
{
    __shared__ float Xs[KC][128];   // [f][n]
    __shared__ float Ws[KC][128];   // [f][d]

    const int n0 = blockIdx.x * 128;
    const int t = threadIdx.x, lane = t & 31, w = t >> 5;
    const int tx = t & 15, ty = t >> 4;

    const int nl = t >> 1;          // local n row this thread loads
    const int fg = t & 1;           // which 8-float half of the KC=16 chunk
    const int nglob = n0 + nl;      // flattened b*N + n
    const float invdeg = 1.0f / (float)g_deg[nglob];

    ull acc[8][4];
    #pragma unroll
    for (int j = 0; j < 8; j++)
        #pragma unroll
        for (int p = 0; p < 4; p++) acc[j][p] = pack2(0.f, 0.f);

    for (int k0 = 0; k0 < 2 * D_; k0 += KC) {
        const float* src = (k0 < D_)
            ? (emb + (size_t)nglob * D_ + k0)
            : (g_S + (size_t)nglob * D_ + (k0 - D_));
        const float scale = (k0 < D_) ? 1.0f : invdeg;
        float4 x0 = *(const float4*)(src + fg * 8);
        float4 x1 = *(const float4*)(src + fg * 8 + 4);
        float4 w0 = *(const float4*)(g_Wt + (size_t)(k0 + w) * 128 + lane * 4);
        float4 w1 = *(const float4*)(g_Wt + (size_t)(k0 + w + 8) * 128 + lane * 4);

        __syncthreads();
        int f0 = fg * 8;
        Xs[f0 + 0][nl] = x0.x * scale;  Xs[f0 + 1][nl] = x0.y * scale;
        Xs[f0 + 2][nl] = x0.z * scale;  Xs[f0 + 3][nl] = x0.w * scale;
        Xs[f0 + 4][nl] = x1.x * scale;  Xs[f0 + 5][nl] = x1.y * scale;
        Xs[f0 + 6][nl] = x1.z * scale;  Xs[f0 + 7][nl] = x1.w * scale;
        *(float4*)&Ws[w][lane * 4] = w0;
        *(float4*)&Ws[w + 8][lane * 4] = w1;
        __syncthreads();

        #pragma unroll
        for (int kk = 0; kk < KC; kk++) {
            float4 av0 = *(const float4*)&Xs[kk][ty * 4];
            float4 av1 = *(const float4*)&Xs[kk][64 + ty * 4];
            float4 bv0 = *(const float4*)&Ws[kk][tx * 4];
            float4 bv1 = *(const float4*)&Ws[kk][64 + tx * 4];
            ull bp[4] = { pack2(bv0.x, bv0.y), pack2(bv0.z, bv0.w),
                          pack2(bv1.x, bv1.y), pack2(bv1.z, bv1.w) };
            float aj[8] = { av0.x, av0.y, av0.z, av0.w,
                            av1.x, av1.y, av1.z, av1.w };
            #pragma unroll
            for (int j = 0; j < 8; j++) {
                ull ad = pack2(aj[j], aj[j]);
                #pragma unroll
                for (int p = 0; p < 4; p++) fma2(acc[j][p], ad, bp[p]);
            }
        }
    }

    float4 bb0 = *(const float4*)(bias + tx * 4);
    float4 bb1 = *(const float4*)(bias + 64 + tx * 4);

    #pragma unroll
    for (int j = 0; j < 8; j++) {
        int nn = (j < 4) ? (ty * 4 + j) : (64 + ty * 4 + (j - 4));
        float* Or = out + (size_t)(n0 + nn) * D_;
        float2 p0 = unpack2(acc[j][0]), p1 = unpack2(acc[j][1]);
        float2 p2 = unpack2(acc[j][2]), p3 = unpack2(acc[j][3]);
        float4 lo = make_float4(fmaxf(p0.x + bb0.x, 0.f), fmaxf(p0.y + bb0.y, 0.f),
                                fmaxf(p1.x + bb0.z, 0.f), fmaxf(p1.y + bb0.w, 0.f));
        float4 hi = make_float4(fmaxf(p2.x + bb1.x, 0.f), fmaxf(p2.y + bb1.y, 0.f),
                                fmaxf(p3.x + bb1.z, 0.f), fmaxf(p3.y + bb1.w, 0.f));
        *(float4*)(Or + tx * 4) = lo;
        *(float4*)(Or + 64 + tx * 4) = hi;
    }
}

// ---------------------------------------------------------------------------
extern "C" void kernel_launch(void* const* d_in, const int* in_sizes, int n_in,
                              void* d_out, int out_size)
{
    const float *emb = nullptr, *cost = nullptr, *W = nullptr, *bias = nullptr;
    for (int i = 0; i < n_in; i++) {
        int s = in_sizes[i];
        if      (s == B_ * N_ * N_) cost = (const float*)d_in[i];
        else if (s == B_ * N_ * D_) emb  = (const float*)d_in[i];
        else if (s == 2 * D_ * D_)  W    = (const float*)d_in[i];
        else if (s == D_)           bias = (const float*)d_in[i];
    }

    prep_kernel<<<128, 256>>>(W);
    gemm1_kernel<<<dim3(16, 8), 256>>>(cost, emb);
    gemm2_kernel<<<128, 256>>>(emb, bias, (float*)d_out);
}

// round 4
// speedup vs baseline: 1.7644x; 1.7644x over previous
#include <cuda_runtime.h>
#include <cuda_fp16.h>
#include <cstdint>

#define B_ 8
#define N_ 2048
#define D_ 128
#define NC 128                // 2048 / 16 k-chunks
#define APITCH 136            // halfs per A row (16 k-rows x 128 j + pad) -> 272B
#define BPITCH 24             // halfs per B row (128 d-rows x 16 k + pad) -> 48B

// ---------------------------------------------------------------------------
// Device scratch (no runtime allocation allowed)
// ---------------------------------------------------------------------------
__device__ float g_S[B_ * N_ * D_];     // un-normalized sum_neighbors (32 MB)
__device__ int   g_deg[B_ * N_];        // nnz per cost row
__device__ float g_Wt[2 * D_ * D_];     // W transposed: Wt[f][d]
__device__ float g_Bt[B_ * D_ * N_];    // emb transposed: Bt[b][d][i] (8 MB)

typedef unsigned long long ull;

// ---------------------------------------------------------------------------
// helpers
// ---------------------------------------------------------------------------
__device__ __forceinline__ void hmma(float* c, const uint32_t* a, const uint32_t* b) {
    asm volatile(
        "mma.sync.aligned.m16n8k16.row.col.f32.f16.f16.f32 "
        "{%0,%1,%2,%3}, {%4,%5,%6,%7}, {%8,%9}, {%0,%1,%2,%3};"
        : "+f"(c[0]), "+f"(c[1]), "+f"(c[2]), "+f"(c[3])
        : "r"(a[0]), "r"(a[1]), "r"(a[2]), "r"(a[3]), "r"(b[0]), "r"(b[1]));
}
__device__ __forceinline__ void ldsm4(uint32_t* r, uint32_t addr) {
    asm volatile("ldmatrix.sync.aligned.m8n8.x4.shared.b16 {%0,%1,%2,%3}, [%4];"
                 : "=r"(r[0]), "=r"(r[1]), "=r"(r[2]), "=r"(r[3]) : "r"(addr));
}
__device__ __forceinline__ void ldsm4t(uint32_t* r, uint32_t addr) {
    asm volatile("ldmatrix.sync.aligned.m8n8.x4.trans.shared.b16 {%0,%1,%2,%3}, [%4];"
                 : "=r"(r[0]), "=r"(r[1]), "=r"(r[2]), "=r"(r[3]) : "r"(addr));
}
__device__ __forceinline__ uint32_t sm_addr(const void* p) {
    return (uint32_t)__cvta_generic_to_shared(p);
}
// exact fp32 -> fp16 hi/lo split of a float4, packed as half2 words
__device__ __forceinline__ void split_f4(float4 v, uint32_t& h0, uint32_t& h1,
                                         uint32_t& l0, uint32_t& l1) {
    __half2 a = __floats2half2_rn(v.x, v.y);
    __half2 b = __floats2half2_rn(v.z, v.w);
    float2 af = __half22float2(a), bf = __half22float2(b);
    __half2 c = __floats2half2_rn(v.x - af.x, v.y - af.y);
    __half2 d = __floats2half2_rn(v.z - bf.x, v.w - bf.y);
    h0 = *(uint32_t*)&a; h1 = *(uint32_t*)&b;
    l0 = *(uint32_t*)&c; l1 = *(uint32_t*)&d;
}
// f32x2 helpers for the SIMT gemm2
__device__ __forceinline__ ull pack2(float lo, float hi) {
    ull r; asm("mov.b64 %0, {%1,%2};" : "=l"(r) : "f"(lo), "f"(hi)); return r;
}
__device__ __forceinline__ void fma2(ull& d, ull a, ull b) {
    asm("fma.rn.f32x2 %0, %1, %2, %3;" : "=l"(d) : "l"(a), "l"(b), "l"(d));
}
__device__ __forceinline__ float2 unpack2(ull v) {
    float2 r; asm("mov.b64 {%0,%1}, %2;" : "=f"(r.x), "=f"(r.y) : "l"(v)); return r;
}

// ---------------------------------------------------------------------------
// prep: zero degree counters, transpose W into Wt[f][d]
// ---------------------------------------------------------------------------
__global__ void prep_kernel(const float* __restrict__ W) {
    int i = blockIdx.x * 256 + threadIdx.x;
    if (i < B_ * N_) g_deg[i] = 0;
    if (i < 2 * D_ * D_) {
        int f = i >> 7, d = i & 127;
        g_Wt[i] = W[d * 2 * D_ + f];
    }
}

// ---------------------------------------------------------------------------
// prep2: transpose emb[b][i][d] -> g_Bt[b][d][i]
// ---------------------------------------------------------------------------
__global__ void prep2_kernel(const float* __restrict__ emb) {
    __shared__ float tile[32][33];
    int b = blockIdx.z;
    int i0 = blockIdx.x * 32;
    int d0 = blockIdx.y * 32;
    int tx = threadIdx.x, ty = threadIdx.y;   // (32, 8)
    const float* eB = emb + (size_t)b * N_ * D_;
    #pragma unroll
    for (int r = 0; r < 32; r += 8)
        tile[ty + r][tx] = eB[(size_t)(i0 + ty + r) * D_ + d0 + tx];
    __syncthreads();
    #pragma unroll
    for (int r = 0; r < 32; r += 8) {
        size_t o = (size_t)b * D_ * N_ + (size_t)(d0 + ty + r) * N_ + i0 + tx;
        g_Bt[o] = tile[tx][ty + r];
    }
}

// ---------------------------------------------------------------------------
// gemm1 on mma.sync fp16 hi/lo split (3 terms, ~2^-22 accuracy).
// C[j][d] = sum_k cost[k][j0+j] * Bt[d][k].  CTA tile 128x128, K-chunk 16.
// A smem: k-major [k][j] (direct coalesced store), ldmatrix.x4.trans.
// B smem: [d][k], ldmatrix.x4.  Fused degree count on cost loads.
// ---------------------------------------------------------------------------
__global__ __launch_bounds__(256, 1) void gemm1_mma_kernel(const float* __restrict__ cost)
{
    __shared__ __align__(16) __half sA[2][2][16 * APITCH];   // [stage][hi/lo]
    __shared__ __align__(16) __half sB[2][2][128 * BPITCH];

    const int tid = threadIdx.x, lane = tid & 31, w = tid >> 5;
    const int b = blockIdx.y, j0 = blockIdx.x * 128;
    const float* cB = cost + (size_t)b * N_ * N_;
    const float* bT = g_Bt + (size_t)b * D_ * N_;

    // load-role indices
    const int kkA = w;                 // this warp loads cost rows kkA, kkA+8
    const int jq  = lane;              // j-quad within the 128-wide tile
    const int dB0 = tid >> 2;          // B rows dB0 and dB0+64
    const int kqB = tid & 3;

    // mma-role indices
    const int wm = w & 3, wn = w >> 2;       // warp tile: m=wm*32, n=wn*64
    const int m0w = wm * 32, n0w = wn * 64;
    const int rsel = (lane & 7) + ((lane & 16) ? 8 : 0);
    const int csel = (lane & 8) ? 8 : 0;

    float acc[2][8][4];
    #pragma unroll
    for (int mi = 0; mi < 2; mi++)
        #pragma unroll
        for (int ni = 0; ni < 8; ni++)
            #pragma unroll
            for (int q = 0; q < 4; q++) acc[mi][ni][q] = 0.f;

    float4 ca0, ca1, eb0, eb1;

    // ---- prologue: load + store chunk 0 ----
    {
        const int i0 = 0;
        ca0 = *(const float4*)(cB + (size_t)(i0 + kkA) * N_ + j0 + jq * 4);
        ca1 = *(const float4*)(cB + (size_t)(i0 + kkA + 8) * N_ + j0 + jq * 4);
        eb0 = *(const float4*)(bT + (size_t)dB0 * N_ + i0 + kqB * 4);
        eb1 = *(const float4*)(bT + (size_t)(dB0 + 64) * N_ + i0 + kqB * 4);
        int nz0 = __popc(__ballot_sync(~0u, ca0.x != 0.f)) + __popc(__ballot_sync(~0u, ca0.y != 0.f))
                + __popc(__ballot_sync(~0u, ca0.z != 0.f)) + __popc(__ballot_sync(~0u, ca0.w != 0.f));
        int nz1 = __popc(__ballot_sync(~0u, ca1.x != 0.f)) + __popc(__ballot_sync(~0u, ca1.y != 0.f))
                + __popc(__ballot_sync(~0u, ca1.z != 0.f)) + __popc(__ballot_sync(~0u, ca1.w != 0.f));
        if (lane == 0) atomicAdd(&g_deg[b * N_ + i0 + kkA], nz0);
        if (lane == 1) atomicAdd(&g_deg[b * N_ + i0 + kkA + 8], nz1);

        uint32_t h0, h1, l0, l1;
        split_f4(ca0, h0, h1, l0, l1);
        *(uint2*)&sA[0][0][kkA * APITCH + jq * 4] = make_uint2(h0, h1);
        *(uint2*)&sA[0][1][kkA * APITCH + jq * 4] = make_uint2(l0, l1);
        split_f4(ca1, h0, h1, l0, l1);
        *(uint2*)&sA[0][0][(kkA + 8) * APITCH + jq * 4] = make_uint2(h0, h1);
        *(uint2*)&sA[0][1][(kkA + 8) * APITCH + jq * 4] = make_uint2(l0, l1);
        split_f4(eb0, h0, h1, l0, l1);
        *(uint2*)&sB[0][0][dB0 * BPITCH + kqB * 4] = make_uint2(h0, h1);
        *(uint2*)&sB[0][1][dB0 * BPITCH + kqB * 4] = make_uint2(l0, l1);
        split_f4(eb1, h0, h1, l0, l1);
        *(uint2*)&sB[0][0][(dB0 + 64) * BPITCH + kqB * 4] = make_uint2(h0, h1);
        *(uint2*)&sB[0][1][(dB0 + 64) * BPITCH + kqB * 4] = make_uint2(l0, l1);
    }
    __syncthreads();

    // ---- main loop ----
    for (int c = 0; c < NC; c++) {
        const int s = c & 1;
        const bool more = (c + 1 < NC);
        if (more) {
            const int i0 = (c + 1) * 16;
            ca0 = *(const float4*)(cB + (size_t)(i0 + kkA) * N_ + j0 + jq * 4);
            ca1 = *(const float4*)(cB + (size_t)(i0 + kkA + 8) * N_ + j0 + jq * 4);
            eb0 = *(const float4*)(bT + (size_t)dB0 * N_ + i0 + kqB * 4);
            eb1 = *(const float4*)(bT + (size_t)(dB0 + 64) * N_ + i0 + kqB * 4);
        }

        // consume stage s
        uint32_t ah[2][4], al[2][4], bh[4][4], bl[4][4];
        #pragma unroll
        for (int mi = 0; mi < 2; mi++) {
            uint32_t a = sm_addr(&sA[s][0][rsel * APITCH + m0w + mi * 16 + csel]);
            ldsm4t(ah[mi], a);
            uint32_t a2 = sm_addr(&sA[s][1][rsel * APITCH + m0w + mi * 16 + csel]);
            ldsm4t(al[mi], a2);
        }
        #pragma unroll
        for (int nq = 0; nq < 4; nq++) {
            uint32_t a = sm_addr(&sB[s][0][(n0w + nq * 16 + rsel) * BPITCH + csel]);
            ldsm4(bh[nq], a);
            uint32_t a2 = sm_addr(&sB[s][1][(n0w + nq * 16 + rsel) * BPITCH + csel]);
            ldsm4(bl[nq], a2);
        }
        #pragma unroll
        for (int mi = 0; mi < 2; mi++)
            #pragma unroll
            for (int ni = 0; ni < 8; ni++) {
                const uint32_t* BH = &bh[ni >> 1][(ni & 1) * 2];
                const uint32_t* BL = &bl[ni >> 1][(ni & 1) * 2];
                hmma(acc[mi][ni], ah[mi], BH);
                hmma(acc[mi][ni], ah[mi], BL);
                hmma(acc[mi][ni], al[mi], BH);
            }

        if (more) {
            const int i0 = (c + 1) * 16;
            int nz0 = __popc(__ballot_sync(~0u, ca0.x != 0.f)) + __popc(__ballot_sync(~0u, ca0.y != 0.f))
                    + __popc(__ballot_sync(~0u, ca0.z != 0.f)) + __popc(__ballot_sync(~0u, ca0.w != 0.f));
            int nz1 = __popc(__ballot_sync(~0u, ca1.x != 0.f)) + __popc(__ballot_sync(~0u, ca1.y != 0.f))
                    + __popc(__ballot_sync(~0u, ca1.z != 0.f)) + __popc(__ballot_sync(~0u, ca1.w != 0.f));
            if (lane == 0) atomicAdd(&g_deg[b * N_ + i0 + kkA], nz0);
            if (lane == 1) atomicAdd(&g_deg[b * N_ + i0 + kkA + 8], nz1);

            const int ns = s ^ 1;
            uint32_t h0, h1, l0, l1;
            split_f4(ca0, h0, h1, l0, l1);
            *(uint2*)&sA[ns][0][kkA * APITCH + jq * 4] = make_uint2(h0, h1);
            *(uint2*)&sA[ns][1][kkA * APITCH + jq * 4] = make_uint2(l0, l1);
            split_f4(ca1, h0, h1, l0, l1);
            *(uint2*)&sA[ns][0][(kkA + 8) * APITCH + jq * 4] = make_uint2(h0, h1);
            *(uint2*)&sA[ns][1][(kkA + 8) * APITCH + jq * 4] = make_uint2(l0, l1);
            split_f4(eb0, h0, h1, l0, l1);
            *(uint2*)&sB[ns][0][dB0 * BPITCH + kqB * 4] = make_uint2(h0, h1);
            *(uint2*)&sB[ns][1][dB0 * BPITCH + kqB * 4] = make_uint2(l0, l1);
            split_f4(eb1, h0, h1, l0, l1);
            *(uint2*)&sB[ns][0][(dB0 + 64) * BPITCH + kqB * 4] = make_uint2(h0, h1);
            *(uint2*)&sB[ns][1][(dB0 + 64) * BPITCH + kqB * 4] = make_uint2(l0, l1);
        }
        __syncthreads();
    }

    // ---- epilogue: fragments -> g_S[b][j][d] ----
    float* Sr = g_S + ((size_t)(b * N_ + j0)) * D_;
    #pragma unroll
    for (int mi = 0; mi < 2; mi++) {
        int r = m0w + mi * 16 + (lane >> 2);
        #pragma unroll
        for (int ni = 0; ni < 8; ni++) {
            int cix = n0w + ni * 8 + 2 * (lane & 3);
            *(float2*)(Sr + (size_t)r * D_ + cix)       = make_float2(acc[mi][ni][0], acc[mi][ni][1]);
            *(float2*)(Sr + (size_t)(r + 8) * D_ + cix) = make_float2(acc[mi][ni][2], acc[mi][ni][3]);
        }
    }
}

// ---------------------------------------------------------------------------
// gemm2 (SIMT f32x2): out[n,d] = relu( X[n,:] @ Wt + bias )
//   X[n,f] = (f < 128) ? emb[n,f] : S[n,f-128] / degree[n]
// ---------------------------------------------------------------------------
#define KC 16
__global__ __launch_bounds__(256, 2) void gemm2_kernel(
    const float* __restrict__ emb, const float* __restrict__ bias,
    float* __restrict__ out)
{
    __shared__ float Xs[KC][128];
    __shared__ float Ws[KC][128];

    const int n0 = blockIdx.x * 128;
    const int t = threadIdx.x, lane = t & 31, w = t >> 5;
    const int tx = t & 15, ty = t >> 4;

    const int nl = t >> 1;
    const int fg = t & 1;
    const int nglob = n0 + nl;
    const float invdeg = 1.0f / (float)g_deg[nglob];

    ull acc[8][4];
    #pragma unroll
    for (int j = 0; j < 8; j++)
        #pragma unroll
        for (int p = 0; p < 4; p++) acc[j][p] = pack2(0.f, 0.f);

    for (int k0 = 0; k0 < 2 * D_; k0 += KC) {
        const float* src = (k0 < D_)
            ? (emb + (size_t)nglob * D_ + k0)
            : (g_S + (size_t)nglob * D_ + (k0 - D_));
        const float scale = (k0 < D_) ? 1.0f : invdeg;
        float4 x0 = *(const float4*)(src + fg * 8);
        float4 x1 = *(const float4*)(src + fg * 8 + 4);
        float4 w0 = *(const float4*)(g_Wt + (size_t)(k0 + w) * 128 + lane * 4);
        float4 w1 = *(const float4*)(g_Wt + (size_t)(k0 + w + 8) * 128 + lane * 4);

        __syncthreads();
        int f0 = fg * 8;
        Xs[f0 + 0][nl] = x0.x * scale;  Xs[f0 + 1][nl] = x0.y * scale;
        Xs[f0 + 2][nl] = x0.z * scale;  Xs[f0 + 3][nl] = x0.w * scale;
        Xs[f0 + 4][nl] = x1.x * scale;  Xs[f0 + 5][nl] = x1.y * scale;
        Xs[f0 + 6][nl] = x1.z * scale;  Xs[f0 + 7][nl] = x1.w * scale;
        *(float4*)&Ws[w][lane * 4] = w0;
        *(float4*)&Ws[w + 8][lane * 4] = w1;
        __syncthreads();

        #pragma unroll
        for (int kk = 0; kk < KC; kk++) {
            float4 av0 = *(const float4*)&Xs[kk][ty * 4];
            float4 av1 = *(const float4*)&Xs[kk][64 + ty * 4];
            float4 bv0 = *(const float4*)&Ws[kk][tx * 4];
            float4 bv1 = *(const float4*)&Ws[kk][64 + tx * 4];
            ull bp[4] = { pack2(bv0.x, bv0.y), pack2(bv0.z, bv0.w),
                          pack2(bv1.x, bv1.y), pack2(bv1.z, bv1.w) };
            float aj[8] = { av0.x, av0.y, av0.z, av0.w,
                            av1.x, av1.y, av1.z, av1.w };
            #pragma unroll
            for (int j = 0; j < 8; j++) {
                ull ad = pack2(aj[j], aj[j]);
                #pragma unroll
                for (int p = 0; p < 4; p++) fma2(acc[j][p], ad, bp[p]);
            }
        }
    }

    float4 bb0 = *(const float4*)(bias + tx * 4);
    float4 bb1 = *(const float4*)(bias + 64 + tx * 4);

    #pragma unroll
    for (int j = 0; j < 8; j++) {
        int nn = (j < 4) ? (ty * 4 + j) : (64 + ty * 4 + (j - 4));
        float* Or = out + (size_t)(n0 + nn) * D_;
        float2 p0 = unpack2(acc[j][0]), p1 = unpack2(acc[j][1]);
        float2 p2 = unpack2(acc[j][2]), p3 = unpack2(acc[j][3]);
        float4 lo = make_float4(fmaxf(p0.x + bb0.x, 0.f), fmaxf(p0.y + bb0.y, 0.f),
                                fmaxf(p1.x + bb0.z, 0.f), fmaxf(p1.y + bb0.w, 0.f));
        float4 hi = make_float4(fmaxf(p2.x + bb1.x, 0.f), fmaxf(p2.y + bb1.y, 0.f),
                                fmaxf(p3.x + bb1.z, 0.f), fmaxf(p3.y + bb1.w, 0.f));
        *(float4*)(Or + tx * 4) = lo;
        *(float4*)(Or + 64 + tx * 4) = hi;
    }
}

// ---------------------------------------------------------------------------
extern "C" void kernel_launch(void* const* d_in, const int* in_sizes, int n_in,
                              void* d_out, int out_size)
{
    const float *emb = nullptr, *cost = nullptr, *W = nullptr, *bias = nullptr;
    for (int i = 0; i < n_in; i++) {
        int s = in_sizes[i];
        if      (s == B_ * N_ * N_) cost = (const float*)d_in[i];
        else if (s == B_ * N_ * D_) emb  = (const float*)d_in[i];
        else if (s == 2 * D_ * D_)  W    = (const float*)d_in[i];
        else if (s == D_)           bias = (const float*)d_in[i];
    }

    prep_kernel<<<128, 256>>>(W);
    prep2_kernel<<<dim3(N_ / 32, D_ / 32, B_), dim3(32, 8)>>>(emb);
    gemm1_mma_kernel<<<dim3(16, 8), 256>>>(cost);
    gemm2_kernel<<<128, 256>>>(emb, bias, (float*)d_out);
}